// round 1
// baseline (speedup 1.0000x reference)
#include <cuda_runtime.h>
#include <math.h>

#define D_MODEL 1024
#define N_HEADS 16
#define DK      64
#define BATCH   4
#define SEQ     2048
#define M_TOTAL (BATCH * SEQ)   // 8192

// ---------------------------------------------------------------------------
// Scratch (static device globals; allocation inside kernel_launch is banned)
// ---------------------------------------------------------------------------
__device__ float g_q[M_TOTAL * D_MODEL];
__device__ float g_k[M_TOTAL * D_MODEL];
__device__ float g_v[M_TOTAL * D_MODEL];
__device__ float g_att[M_TOTAL * D_MODEL];

// ---------------------------------------------------------------------------
// NT GEMM with bias:  out[m,n] = sum_k X[m,k] * W[n,k] + b[n]
// X: [M, K] row-major, W: [N, K] row-major (torch Linear weight layout)
// Tiles: 64x64 output, BK=16, 256 threads, 4x4 per thread.
// ---------------------------------------------------------------------------
#define GBM 64
#define GBN 64
#define GBK 16

__global__ __launch_bounds__(256) void gemm_nt_bias(
    const float* __restrict__ X, const float* __restrict__ W,
    const float* __restrict__ bias, float* __restrict__ out,
    int M, int N, int K)
{
    __shared__ float Xs[GBK][GBM + 4];
    __shared__ float Ws[GBK][GBN + 4];

    const int bm = blockIdx.y * GBM;
    const int bn = blockIdx.x * GBN;
    const int tid = threadIdx.x;

    const int tm = (tid / 16) * 4;   // 0..60
    const int tn = (tid % 16) * 4;   // 0..60

    const int lr = tid / 4;          // 0..63  (row within tile)
    const int lk = (tid % 4) * 4;    // 0,4,8,12 (k within BK)

    float acc[4][4];
#pragma unroll
    for (int i = 0; i < 4; i++)
#pragma unroll
        for (int j = 0; j < 4; j++) acc[i][j] = 0.f;

    const float* Xp = X + (size_t)(bm + lr) * K + lk;
    const float* Wp = W + (size_t)(bn + lr) * K + lk;

    for (int k0 = 0; k0 < K; k0 += GBK) {
        float4 xv = *(const float4*)(Xp + k0);
        float4 wv = *(const float4*)(Wp + k0);
        Xs[lk + 0][lr] = xv.x; Xs[lk + 1][lr] = xv.y;
        Xs[lk + 2][lr] = xv.z; Xs[lk + 3][lr] = xv.w;
        Ws[lk + 0][lr] = wv.x; Ws[lk + 1][lr] = wv.y;
        Ws[lk + 2][lr] = wv.z; Ws[lk + 3][lr] = wv.w;
        __syncthreads();

#pragma unroll
        for (int k = 0; k < GBK; k++) {
            float4 a = *(const float4*)&Xs[k][tm];
            float4 b = *(const float4*)&Ws[k][tn];
            float av[4] = {a.x, a.y, a.z, a.w};
            float bv[4] = {b.x, b.y, b.z, b.w};
#pragma unroll
            for (int i = 0; i < 4; i++)
#pragma unroll
                for (int j = 0; j < 4; j++)
                    acc[i][j] = fmaf(av[i], bv[j], acc[i][j]);
        }
        __syncthreads();
    }

    const float4 bv4 = *(const float4*)&bias[bn + tn];
    const float bb[4] = {bv4.x, bv4.y, bv4.z, bv4.w};
#pragma unroll
    for (int i = 0; i < 4; i++) {
        float4 o;
        o.x = acc[i][0] + bb[0];
        o.y = acc[i][1] + bb[1];
        o.z = acc[i][2] + bb[2];
        o.w = acc[i][3] + bb[3];
        *(float4*)&out[(size_t)(bm + tm + i) * N + bn + tn] = o;
    }
}

// ---------------------------------------------------------------------------
// Causal flash attention, fp32 SIMT.
// One thread per query row (64 rows / block). q and o live in registers;
// K/V tiles (64 keys x 64 dims) staged in smem, read via broadcast
// (all threads read the same (j,d) -> conflict-free).
// Online softmax updated per 16-key chunk.
// Layout of projected tensors: [B*S, D_MODEL], head h at columns h*64..h*64+63.
// ---------------------------------------------------------------------------
__global__ __launch_bounds__(64) void attn_kernel(
    const float* __restrict__ Qp, const float* __restrict__ Kp,
    const float* __restrict__ Vp, float* __restrict__ Op)
{
    const int qtile = blockIdx.x;   // 0..31
    const int h     = blockIdx.y;   // 0..15
    const int b     = blockIdx.z;   // 0..3
    const int r     = threadIdx.x;  // 0..63

    const int qi   = qtile * 64 + r;          // query index within sequence
    const size_t rowQ = (size_t)(b * SEQ + qi);

    __shared__ float Ks[64][DK];
    __shared__ float Vs[64][DK];

    // Load q row into registers, pre-scaled by 1/sqrt(Dk) = 0.125
    float q[DK];
    {
        const float* qrow = Qp + rowQ * D_MODEL + h * DK;
#pragma unroll
        for (int d = 0; d < DK; d += 4) {
            float4 v = *(const float4*)(qrow + d);
            q[d + 0] = v.x * 0.125f;
            q[d + 1] = v.y * 0.125f;
            q[d + 2] = v.z * 0.125f;
            q[d + 3] = v.w * 0.125f;
        }
    }

    float o[DK];
#pragma unroll
    for (int d = 0; d < DK; d++) o[d] = 0.f;
    float m = -INFINITY;
    float l = 0.f;

    for (int kt = 0; kt <= qtile; kt++) {
        __syncthreads();
        // cooperative tile load: 64x64 floats each for K and V
        {
            const float* kbase = Kp + (size_t)(b * SEQ + kt * 64) * D_MODEL + h * DK;
            const float* vbase = Vp + (size_t)(b * SEQ + kt * 64) * D_MODEL + h * DK;
#pragma unroll
            for (int it = 0; it < 16; it++) {
                int idx = it * 64 + threadIdx.x;       // 0..1023 float4 slots
                int row = idx >> 4;                    // /16
                int c   = (idx & 15) * 4;
                float4 kv = *(const float4*)(kbase + (size_t)row * D_MODEL + c);
                float4 vv = *(const float4*)(vbase + (size_t)row * D_MODEL + c);
                *(float4*)&Ks[row][c] = kv;
                *(float4*)&Vs[row][c] = vv;
            }
        }
        __syncthreads();

        const bool diag = (kt == qtile);

        for (int jj0 = 0; jj0 < 64; jj0 += 16) {
            if (diag && jj0 > r) break;   // chunk fully masked for this row

            float s[16];
#pragma unroll
            for (int u = 0; u < 16; u++) {
                float acc = 0.f;
#pragma unroll
                for (int d = 0; d < DK; d++)
                    acc = fmaf(q[d], Ks[jj0 + u][d], acc);
                s[u] = acc;
            }
            if (diag) {
#pragma unroll
                for (int u = 0; u < 16; u++)
                    if (jj0 + u > r) s[u] = -INFINITY;
            }

            float mc = s[0];
#pragma unroll
            for (int u = 1; u < 16; u++) mc = fmaxf(mc, s[u]);
            const float mn = fmaxf(m, mc);
            const float scale = __expf(m - mn);   // 0 if m was -inf
            l *= scale;
#pragma unroll
            for (int d = 0; d < DK; d++) o[d] *= scale;

#pragma unroll
            for (int u = 0; u < 16; u++) {
                const float p = __expf(s[u] - mn);
                l += p;
#pragma unroll
                for (int d = 0; d < DK; d++)
                    o[d] = fmaf(p, Vs[jj0 + u][d], o[d]);
            }
            m = mn;
        }
    }

    const float inv = 1.f / l;
    float* orow = Op + rowQ * D_MODEL + h * DK;
#pragma unroll
    for (int d = 0; d < DK; d += 4) {
        float4 v;
        v.x = o[d + 0] * inv;
        v.y = o[d + 1] * inv;
        v.z = o[d + 2] * inv;
        v.w = o[d + 3] * inv;
        *(float4*)(orow + d) = v;
    }
}

// ---------------------------------------------------------------------------
// Launch
// Inputs (metadata order): Q, K, V, mask, W_q, b_q, W_k, b_k, W_v, b_v, W_o, b_o
// ---------------------------------------------------------------------------
extern "C" void kernel_launch(void* const* d_in, const int* in_sizes, int n_in,
                              void* d_out, int out_size)
{
    const float* Q   = (const float*)d_in[0];
    const float* K   = (const float*)d_in[1];
    const float* V   = (const float*)d_in[2];
    // d_in[3] = mask (causal; structure exploited directly)
    const float* W_q = (const float*)d_in[4];
    const float* b_q = (const float*)d_in[5];
    const float* W_k = (const float*)d_in[6];
    const float* b_k = (const float*)d_in[7];
    const float* W_v = (const float*)d_in[8];
    const float* b_v = (const float*)d_in[9];
    const float* W_o = (const float*)d_in[10];
    const float* b_o = (const float*)d_in[11];
    float* out = (float*)d_out;

    float *dq, *dk, *dv, *datt;
    cudaGetSymbolAddress((void**)&dq,   g_q);
    cudaGetSymbolAddress((void**)&dk,   g_k);
    cudaGetSymbolAddress((void**)&dv,   g_v);
    cudaGetSymbolAddress((void**)&datt, g_att);

    dim3 gGemm(D_MODEL / GBN, M_TOTAL / GBM);   // (16, 128)

    gemm_nt_bias<<<gGemm, 256>>>(Q, W_q, b_q, dq, M_TOTAL, D_MODEL, D_MODEL);
    gemm_nt_bias<<<gGemm, 256>>>(K, W_k, b_k, dk, M_TOTAL, D_MODEL, D_MODEL);
    gemm_nt_bias<<<gGemm, 256>>>(V, W_v, b_v, dv, M_TOTAL, D_MODEL, D_MODEL);

    dim3 gAttn(SEQ / 64, N_HEADS, BATCH);       // (32, 16, 4)
    attn_kernel<<<gAttn, 64>>>(dq, dk, dv, datt);

    gemm_nt_bias<<<gGemm, 256>>>(datt, W_o, b_o, out, M_TOTAL, D_MODEL, D_MODEL);
}

// round 3
// speedup vs baseline: 2.6289x; 2.6289x over previous
#include <cuda_runtime.h>
#include <cuda_bf16.h>
#include <math.h>
#include <stdint.h>

#define D_MODEL 1024
#define N_HEADS 16
#define DK      64
#define BATCH   4
#define SEQ     2048
#define M_TOTAL (BATCH * SEQ)   // 8192

// ---------------------------------------------------------------------------
// Scratch (static device globals; allocation inside kernel_launch is banned)
// ---------------------------------------------------------------------------
__device__ float g_q[M_TOTAL * D_MODEL];
__device__ float g_k[M_TOTAL * D_MODEL];
__device__ float g_v[M_TOTAL * D_MODEL];
__device__ float g_att[M_TOTAL * D_MODEL];
__device__ __nv_bfloat16 g_xhi[M_TOTAL * D_MODEL];
__device__ __nv_bfloat16 g_xlo[M_TOTAL * D_MODEL];
__device__ __nv_bfloat16 g_whi[D_MODEL * D_MODEL];
__device__ __nv_bfloat16 g_wlo[D_MODEL * D_MODEL];

// ---------------------------------------------------------------------------
// PTX helpers (portable: sm_80+ instructions only, no 'a' features)
// ---------------------------------------------------------------------------
__device__ __forceinline__ uint32_t smem_u32(const void* p) {
    uint32_t a;
    asm("{ .reg .u64 t; cvta.to.shared.u64 t, %1; cvt.u32.u64 %0, t; }"
        : "=r"(a) : "l"(p));
    return a;
}

__device__ __forceinline__ void ldsm4(uint32_t* r, uint32_t addr) {
    asm volatile("ldmatrix.sync.aligned.m8n8.x4.shared.b16 {%0,%1,%2,%3}, [%4];"
                 : "=r"(r[0]), "=r"(r[1]), "=r"(r[2]), "=r"(r[3]) : "r"(addr));
}

__device__ __forceinline__ void mma_bf16(float* c, const uint32_t* a,
                                         uint32_t b0, uint32_t b1) {
    asm volatile(
        "mma.sync.aligned.m16n8k16.row.col.f32.bf16.bf16.f32 "
        "{%0,%1,%2,%3}, {%4,%5,%6,%7}, {%8,%9}, {%0,%1,%2,%3};"
        : "+f"(c[0]), "+f"(c[1]), "+f"(c[2]), "+f"(c[3])
        : "r"(a[0]), "r"(a[1]), "r"(a[2]), "r"(a[3]), "r"(b0), "r"(b1));
}

#define CP_ASYNC16(dst, src) \
    asm volatile("cp.async.cg.shared.global [%0], [%1], 16;" :: "r"(dst), "l"(src))
#define CP_COMMIT()  asm volatile("cp.async.commit_group;" ::: "memory")
#define CP_WAIT1()   asm volatile("cp.async.wait_group 1;" ::: "memory")
#define CP_WAIT0()   asm volatile("cp.async.wait_group 0;" ::: "memory")

// ---------------------------------------------------------------------------
// fp32 -> (bf16 hi, bf16 lo) split
// ---------------------------------------------------------------------------
__global__ __launch_bounds__(256) void split_kernel(
    const float* __restrict__ x, __nv_bfloat16* __restrict__ hi,
    __nv_bfloat16* __restrict__ lo, int n4)
{
    int i = blockIdx.x * blockDim.x + threadIdx.x;
    if (i >= n4) return;
    float4 v = ((const float4*)x)[i];
    __nv_bfloat16 h0 = __float2bfloat16(v.x);
    __nv_bfloat16 h1 = __float2bfloat16(v.y);
    __nv_bfloat16 h2 = __float2bfloat16(v.z);
    __nv_bfloat16 h3 = __float2bfloat16(v.w);
    __nv_bfloat16 l0 = __float2bfloat16(v.x - __bfloat162float(h0));
    __nv_bfloat16 l1 = __float2bfloat16(v.y - __bfloat162float(h1));
    __nv_bfloat16 l2 = __float2bfloat16(v.z - __bfloat162float(h2));
    __nv_bfloat16 l3 = __float2bfloat16(v.w - __bfloat162float(h3));
    __nv_bfloat162* hp = (__nv_bfloat162*)hi;
    __nv_bfloat162* lp = (__nv_bfloat162*)lo;
    hp[2 * i]     = __nv_bfloat162(h0, h1);
    hp[2 * i + 1] = __nv_bfloat162(h2, h3);
    lp[2 * i]     = __nv_bfloat162(l0, l1);
    lp[2 * i + 1] = __nv_bfloat162(l2, l3);
}

// ---------------------------------------------------------------------------
// mma.sync NT GEMM with bias, bf16 2-term split (hi*hi + hi*lo + lo*hi):
//   out[m,n] = sum_k X[m,k]*W[n,k] + bias[n],  M=8192, N=1024, K=1024
// CTA tile 128x128, 8 warps (2 M x 4 N), warp tile 64x32.
// K chunks of 64, double-buffered via cp.async. XOR-swizzled smem + ldmatrix.
// ---------------------------------------------------------------------------
#define TM 128
#define TN 128
#define KC 64
#define NCHUNK (D_MODEL / KC)          // 16
#define STAGE_BYTES (4 * 128 * 128)    // Ahi|Alo|Bhi|Blo, 16KB each = 64KB
#define SM_TOTAL (2 * STAGE_BYTES)     // 128KB

__global__ __launch_bounds__(256, 1) void gemm_mma(
    const __nv_bfloat16* __restrict__ Xhi, const __nv_bfloat16* __restrict__ Xlo,
    const __nv_bfloat16* __restrict__ Whi, const __nv_bfloat16* __restrict__ Wlo,
    const float* __restrict__ bias, float* __restrict__ out)
{
    extern __shared__ __align__(1024) char smem[];
    const uint32_t smem_base = smem_u32(smem);
    const int tid  = threadIdx.x;
    const int wid  = tid >> 5;
    const int lane = tid & 31;
    const int wm   = wid & 1;     // 0..1  -> 64-row slice
    const int wn   = wid >> 1;    // 0..3  -> 32-col slice
    const int bm = blockIdx.y * TM;
    const int bn = blockIdx.x * TN;

    const __nv_bfloat16* srcs[4];
    srcs[0] = Xhi + (size_t)bm * D_MODEL;
    srcs[1] = Xlo + (size_t)bm * D_MODEL;
    srcs[2] = Whi + (size_t)bn * D_MODEL;
    srcs[3] = Wlo + (size_t)bn * D_MODEL;

    // lane-dependent ldmatrix address components
    const int a_row_off  = ((lane >> 3) & 1) * 8 + (lane & 7);
    const int a_unit_off = lane >> 4;                     // 0..1
    const int b_row_off  = ((lane >> 4) & 1) * 8 + (lane & 7);
    const int b_unit_off = (lane >> 3) & 1;               // 0..1

    float acc[4][4][4];
#pragma unroll
    for (int mt = 0; mt < 4; mt++)
#pragma unroll
        for (int nt = 0; nt < 4; nt++)
#pragma unroll
            for (int j = 0; j < 4; j++) acc[mt][nt][j] = 0.f;

    // stage issue helper (inlined by macro-style lambda)
    auto stage_load = [&](int buf, int c) {
        const uint32_t stage = smem_base + buf * STAGE_BYTES;
#pragma unroll
        for (int s = 0; s < 4; ++s) {
#pragma unroll
            for (int i = 0; i < 4; ++i) {
                int idx = i * 256 + tid;
                int row = idx >> 3, u = idx & 7;
                const void* src = srcs[s] + (size_t)row * D_MODEL + c * KC + u * 8;
                uint32_t dst = stage + s * 16384 + row * 128 + ((u ^ (row & 7)) << 4);
                CP_ASYNC16(dst, src);
            }
        }
        CP_COMMIT();
    };

    stage_load(0, 0);

#pragma unroll 1
    for (int c = 0; c < NCHUNK; ++c) {
        if (c + 1 < NCHUNK) { stage_load((c + 1) & 1, c + 1); CP_WAIT1(); }
        else                { CP_WAIT0(); }
        __syncthreads();

        const uint32_t stage = smem_base + (c & 1) * STAGE_BYTES;
        const uint32_t Ah = stage;
        const uint32_t Al = stage + 16384;
        const uint32_t Bh = stage + 32768;
        const uint32_t Bl = stage + 49152;

#pragma unroll
        for (int ks = 0; ks < 4; ++ks) {
            uint32_t ah[4][4], al[4][4], bh[2][4], bl[2][4];
#pragma unroll
            for (int mt = 0; mt < 4; ++mt) {
                int row  = wm * 64 + mt * 16 + a_row_off;
                int unit = ks * 2 + a_unit_off;
                uint32_t off = row * 128 + ((unit ^ (row & 7)) << 4);
                ldsm4(ah[mt], Ah + off);
                ldsm4(al[mt], Al + off);
            }
#pragma unroll
            for (int nh = 0; nh < 2; ++nh) {
                int row  = wn * 32 + nh * 16 + b_row_off;
                int unit = ks * 2 + b_unit_off;
                uint32_t off = row * 128 + ((unit ^ (row & 7)) << 4);
                ldsm4(bh[nh], Bh + off);
                ldsm4(bl[nh], Bl + off);
            }
#pragma unroll
            for (int mt = 0; mt < 4; ++mt) {
#pragma unroll
                for (int nt = 0; nt < 4; ++nt) {
                    const int nh = nt >> 1, p = (nt & 1) * 2;
                    mma_bf16(acc[mt][nt], ah[mt], bh[nh][p], bh[nh][p + 1]);
                    mma_bf16(acc[mt][nt], ah[mt], bl[nh][p], bl[nh][p + 1]);
                    mma_bf16(acc[mt][nt], al[mt], bh[nh][p], bh[nh][p + 1]);
                }
            }
        }
        __syncthreads();
    }

    // epilogue: C frag layout -> gmem with bias
    const int grow = lane >> 2;
    const int gcol = (lane & 3) * 2;
#pragma unroll
    for (int mt = 0; mt < 4; ++mt) {
#pragma unroll
        for (int nt = 0; nt < 4; ++nt) {
            const int m0 = bm + wm * 64 + mt * 16 + grow;
            const int n0 = bn + wn * 32 + nt * 8 + gcol;
            const float b0 = bias[n0], b1 = bias[n0 + 1];
            float2 v0 = make_float2(acc[mt][nt][0] + b0, acc[mt][nt][1] + b1);
            float2 v1 = make_float2(acc[mt][nt][2] + b0, acc[mt][nt][3] + b1);
            *(float2*)&out[(size_t)m0 * D_MODEL + n0]       = v0;
            *(float2*)&out[(size_t)(m0 + 8) * D_MODEL + n0] = v1;
        }
    }
}

// ---------------------------------------------------------------------------
// Causal flash attention, fp32 SIMT (unchanged from round 1 — passes)
// ---------------------------------------------------------------------------
__global__ __launch_bounds__(64) void attn_kernel(
    const float* __restrict__ Qp, const float* __restrict__ Kp,
    const float* __restrict__ Vp, float* __restrict__ Op)
{
    const int qtile = blockIdx.x;
    const int h     = blockIdx.y;
    const int b     = blockIdx.z;
    const int r     = threadIdx.x;

    const int qi   = qtile * 64 + r;
    const size_t rowQ = (size_t)(b * SEQ + qi);

    __shared__ float Ks[64][DK];
    __shared__ float Vs[64][DK];

    float q[DK];
    {
        const float* qrow = Qp + rowQ * D_MODEL + h * DK;
#pragma unroll
        for (int d = 0; d < DK; d += 4) {
            float4 v = *(const float4*)(qrow + d);
            q[d + 0] = v.x * 0.125f;
            q[d + 1] = v.y * 0.125f;
            q[d + 2] = v.z * 0.125f;
            q[d + 3] = v.w * 0.125f;
        }
    }

    float o[DK];
#pragma unroll
    for (int d = 0; d < DK; d++) o[d] = 0.f;
    float m = -INFINITY;
    float l = 0.f;

    for (int kt = 0; kt <= qtile; kt++) {
        __syncthreads();
        {
            const float* kbase = Kp + (size_t)(b * SEQ + kt * 64) * D_MODEL + h * DK;
            const float* vbase = Vp + (size_t)(b * SEQ + kt * 64) * D_MODEL + h * DK;
#pragma unroll
            for (int it = 0; it < 16; it++) {
                int idx = it * 64 + threadIdx.x;
                int row = idx >> 4;
                int c   = (idx & 15) * 4;
                float4 kv = *(const float4*)(kbase + (size_t)row * D_MODEL + c);
                float4 vv = *(const float4*)(vbase + (size_t)row * D_MODEL + c);
                *(float4*)&Ks[row][c] = kv;
                *(float4*)&Vs[row][c] = vv;
            }
        }
        __syncthreads();

        const bool diag = (kt == qtile);

        for (int jj0 = 0; jj0 < 64; jj0 += 16) {
            if (diag && jj0 > r) break;

            float s[16];
#pragma unroll
            for (int u = 0; u < 16; u++) {
                float acc = 0.f;
#pragma unroll
                for (int d = 0; d < DK; d++)
                    acc = fmaf(q[d], Ks[jj0 + u][d], acc);
                s[u] = acc;
            }
            if (diag) {
#pragma unroll
                for (int u = 0; u < 16; u++)
                    if (jj0 + u > r) s[u] = -INFINITY;
            }

            float mc = s[0];
#pragma unroll
            for (int u = 1; u < 16; u++) mc = fmaxf(mc, s[u]);
            const float mn = fmaxf(m, mc);
            const float scale = __expf(m - mn);
            l *= scale;
#pragma unroll
            for (int d = 0; d < DK; d++) o[d] *= scale;

#pragma unroll
            for (int u = 0; u < 16; u++) {
                const float p = __expf(s[u] - mn);
                l += p;
#pragma unroll
                for (int d = 0; d < DK; d++)
                    o[d] = fmaf(p, Vs[jj0 + u][d], o[d]);
            }
            m = mn;
        }
    }

    const float inv = 1.f / l;
    float* orow = Op + rowQ * D_MODEL + h * DK;
#pragma unroll
    for (int d = 0; d < DK; d += 4) {
        float4 v;
        v.x = o[d + 0] * inv;
        v.y = o[d + 1] * inv;
        v.z = o[d + 2] * inv;
        v.w = o[d + 3] * inv;
        *(float4*)(orow + d) = v;
    }
}

// ---------------------------------------------------------------------------
// Launch
// Inputs (metadata order): Q, K, V, mask, W_q, b_q, W_k, b_k, W_v, b_v, W_o, b_o
// ---------------------------------------------------------------------------
extern "C" void kernel_launch(void* const* d_in, const int* in_sizes, int n_in,
                              void* d_out, int out_size)
{
    const float* Q   = (const float*)d_in[0];
    const float* K   = (const float*)d_in[1];
    const float* V   = (const float*)d_in[2];
    const float* W_q = (const float*)d_in[4];
    const float* b_q = (const float*)d_in[5];
    const float* W_k = (const float*)d_in[6];
    const float* b_k = (const float*)d_in[7];
    const float* W_v = (const float*)d_in[8];
    const float* b_v = (const float*)d_in[9];
    const float* W_o = (const float*)d_in[10];
    const float* b_o = (const float*)d_in[11];
    float* out = (float*)d_out;

    float *dq, *dk, *dv, *datt;
    __nv_bfloat16 *xhi, *xlo, *whi, *wlo;
    cudaGetSymbolAddress((void**)&dq,   g_q);
    cudaGetSymbolAddress((void**)&dk,   g_k);
    cudaGetSymbolAddress((void**)&dv,   g_v);
    cudaGetSymbolAddress((void**)&datt, g_att);
    cudaGetSymbolAddress((void**)&xhi,  g_xhi);
    cudaGetSymbolAddress((void**)&xlo,  g_xlo);
    cudaGetSymbolAddress((void**)&whi,  g_whi);
    cudaGetSymbolAddress((void**)&wlo,  g_wlo);

    cudaFuncSetAttribute(gemm_mma, cudaFuncAttributeMaxDynamicSharedMemorySize, SM_TOTAL);

    const int nX4 = M_TOTAL * D_MODEL / 4;
    const int nW4 = D_MODEL * D_MODEL / 4;
    const int SPLIT_B = 256;
    dim3 gX((nX4 + SPLIT_B - 1) / SPLIT_B);
    dim3 gW((nW4 + SPLIT_B - 1) / SPLIT_B);
    dim3 gGemm(D_MODEL / TN, M_TOTAL / TM);   // (8, 64)

    // Q projection
    split_kernel<<<gX, SPLIT_B>>>(Q, xhi, xlo, nX4);
    split_kernel<<<gW, SPLIT_B>>>(W_q, whi, wlo, nW4);
    gemm_mma<<<gGemm, 256, SM_TOTAL>>>(xhi, xlo, whi, wlo, b_q, dq);
    // K projection
    split_kernel<<<gX, SPLIT_B>>>(K, xhi, xlo, nX4);
    split_kernel<<<gW, SPLIT_B>>>(W_k, whi, wlo, nW4);
    gemm_mma<<<gGemm, 256, SM_TOTAL>>>(xhi, xlo, whi, wlo, b_k, dk);
    // V projection
    split_kernel<<<gX, SPLIT_B>>>(V, xhi, xlo, nX4);
    split_kernel<<<gW, SPLIT_B>>>(W_v, whi, wlo, nW4);
    gemm_mma<<<gGemm, 256, SM_TOTAL>>>(xhi, xlo, whi, wlo, b_v, dv);

    // attention
    dim3 gAttn(SEQ / 64, N_HEADS, BATCH);
    attn_kernel<<<gAttn, 64>>>(dq, dk, dv, datt);

    // O projection
    split_kernel<<<gX, SPLIT_B>>>(datt, xhi, xlo, nX4);
    split_kernel<<<gW, SPLIT_B>>>(W_o, whi, wlo, nW4);
    gemm_mma<<<gGemm, 256, SM_TOTAL>>>(xhi, xlo, whi, wlo, b_o, out);
}

// round 4
// speedup vs baseline: 6.1026x; 2.3214x over previous
#include <cuda_runtime.h>
#include <cuda_bf16.h>
#include <math.h>
#include <stdint.h>

#define D_MODEL 1024
#define N_HEADS 16
#define DK      64
#define BATCH   4
#define SEQ     2048
#define M_TOTAL (BATCH * SEQ)   // 8192

// ---------------------------------------------------------------------------
// Scratch (static device globals; allocation inside kernel_launch is banned)
// ---------------------------------------------------------------------------
__device__ __nv_bfloat16 g_qhi[M_TOTAL * D_MODEL];
__device__ __nv_bfloat16 g_qlo[M_TOTAL * D_MODEL];
__device__ __nv_bfloat16 g_khi[M_TOTAL * D_MODEL];
__device__ __nv_bfloat16 g_klo[M_TOTAL * D_MODEL];
__device__ __nv_bfloat16 g_vhi[M_TOTAL * D_MODEL];
__device__ __nv_bfloat16 g_vlo[M_TOTAL * D_MODEL];
__device__ __nv_bfloat16 g_xhi[M_TOTAL * D_MODEL];
__device__ __nv_bfloat16 g_xlo[M_TOTAL * D_MODEL];
__device__ __nv_bfloat16 g_whi[D_MODEL * D_MODEL];
__device__ __nv_bfloat16 g_wlo[D_MODEL * D_MODEL];

// ---------------------------------------------------------------------------
// PTX helpers (portable sm_80+ only)
// ---------------------------------------------------------------------------
__device__ __forceinline__ uint32_t smem_u32(const void* p) {
    uint32_t a;
    asm("{ .reg .u64 t; cvta.to.shared.u64 t, %1; cvt.u32.u64 %0, t; }"
        : "=r"(a) : "l"(p));
    return a;
}
__device__ __forceinline__ void ldsm4(uint32_t* r, uint32_t addr) {
    asm volatile("ldmatrix.sync.aligned.m8n8.x4.shared.b16 {%0,%1,%2,%3}, [%4];"
                 : "=r"(r[0]), "=r"(r[1]), "=r"(r[2]), "=r"(r[3]) : "r"(addr));
}
__device__ __forceinline__ void ldsm4t(uint32_t* r, uint32_t addr) {
    asm volatile("ldmatrix.sync.aligned.m8n8.x4.trans.shared.b16 {%0,%1,%2,%3}, [%4];"
                 : "=r"(r[0]), "=r"(r[1]), "=r"(r[2]), "=r"(r[3]) : "r"(addr));
}
__device__ __forceinline__ void mma_bf16(float* c, const uint32_t* a,
                                         uint32_t b0, uint32_t b1) {
    asm volatile(
        "mma.sync.aligned.m16n8k16.row.col.f32.bf16.bf16.f32 "
        "{%0,%1,%2,%3}, {%4,%5,%6,%7}, {%8,%9}, {%0,%1,%2,%3};"
        : "+f"(c[0]), "+f"(c[1]), "+f"(c[2]), "+f"(c[3])
        : "r"(a[0]), "r"(a[1]), "r"(a[2]), "r"(a[3]), "r"(b0), "r"(b1));
}
#define CP_ASYNC16(dst, src) \
    asm volatile("cp.async.cg.shared.global [%0], [%1], 16;" :: "r"(dst), "l"(src))
#define CP_COMMIT()  asm volatile("cp.async.commit_group;" ::: "memory")
#define CP_WAIT1()   asm volatile("cp.async.wait_group 1;" ::: "memory")
#define CP_WAIT0()   asm volatile("cp.async.wait_group 0;" ::: "memory")

// pack hi-bf16 halves of two floats (truncation split): lo half <- a, hi half <- b
__device__ __forceinline__ uint32_t pack_hi(float a, float b) {
    uint32_t r;
    asm("prmt.b32 %0, %1, %2, 0x7632;" : "=r"(r)
        : "r"(__float_as_uint(a)), "r"(__float_as_uint(b)));
    return r;
}
__device__ __forceinline__ float hi_part(float a) {
    return __uint_as_float(__float_as_uint(a) & 0xFFFF0000u);
}
// pack bf16x2 from two floats (RN): lo half <- a, hi half <- b
__device__ __forceinline__ uint32_t pack_rn(float a, float b) {
    uint32_t r;
    asm("cvt.rn.bf16x2.f32 %0, %1, %2;" : "=r"(r) : "f"(b), "f"(a));
    return r;
}

// ---------------------------------------------------------------------------
// fp32 -> (bf16 hi, bf16 lo) split
// ---------------------------------------------------------------------------
__global__ __launch_bounds__(256) void split_kernel(
    const float* __restrict__ x, __nv_bfloat16* __restrict__ hi,
    __nv_bfloat16* __restrict__ lo, int n4)
{
    int i = blockIdx.x * blockDim.x + threadIdx.x;
    if (i >= n4) return;
    float4 v = ((const float4*)x)[i];
    uint32_t* hp = (uint32_t*)hi;
    uint32_t* lp = (uint32_t*)lo;
    hp[2 * i]     = pack_hi(v.x, v.y);
    hp[2 * i + 1] = pack_hi(v.z, v.w);
    lp[2 * i]     = pack_rn(v.x - hi_part(v.x), v.y - hi_part(v.y));
    lp[2 * i + 1] = pack_rn(v.z - hi_part(v.z), v.w - hi_part(v.w));
}

// ---------------------------------------------------------------------------
// mma.sync NT GEMM with bias, bf16 2-term split (hi*hi + hi*lo + lo*hi):
//   out[m,n] = sum_k X[m,k]*W[n,k] + bias[n]
// Epilogue writes either fp32 (outf) or a bf16 hi/lo pair (ohi/olo).
// ---------------------------------------------------------------------------
#define TM 128
#define TN 128
#define KC 64
#define NCHUNK (D_MODEL / KC)          // 16
#define STAGE_BYTES (4 * 128 * 128)    // Ahi|Alo|Bhi|Blo, 16KB each = 64KB
#define SM_TOTAL (2 * STAGE_BYTES)     // 128KB

__global__ __launch_bounds__(256, 1) void gemm_mma(
    const __nv_bfloat16* __restrict__ Xhi, const __nv_bfloat16* __restrict__ Xlo,
    const __nv_bfloat16* __restrict__ Whi, const __nv_bfloat16* __restrict__ Wlo,
    const float* __restrict__ bias, float* __restrict__ outf,
    __nv_bfloat16* __restrict__ ohi, __nv_bfloat16* __restrict__ olo)
{
    extern __shared__ __align__(1024) char smem[];
    const uint32_t smem_base = smem_u32(smem);
    const int tid  = threadIdx.x;
    const int wid  = tid >> 5;
    const int lane = tid & 31;
    const int wm   = wid & 1;
    const int wn   = wid >> 1;
    const int bm = blockIdx.y * TM;
    const int bn = blockIdx.x * TN;

    const __nv_bfloat16* srcs[4];
    srcs[0] = Xhi + (size_t)bm * D_MODEL;
    srcs[1] = Xlo + (size_t)bm * D_MODEL;
    srcs[2] = Whi + (size_t)bn * D_MODEL;
    srcs[3] = Wlo + (size_t)bn * D_MODEL;

    const int a_row_off  = ((lane >> 3) & 1) * 8 + (lane & 7);
    const int a_unit_off = lane >> 4;
    const int b_row_off  = ((lane >> 4) & 1) * 8 + (lane & 7);
    const int b_unit_off = (lane >> 3) & 1;

    float acc[4][4][4];
#pragma unroll
    for (int mt = 0; mt < 4; mt++)
#pragma unroll
        for (int nt = 0; nt < 4; nt++)
#pragma unroll
            for (int j = 0; j < 4; j++) acc[mt][nt][j] = 0.f;

    auto stage_load = [&](int buf, int c) {
        const uint32_t stage = smem_base + buf * STAGE_BYTES;
#pragma unroll
        for (int s = 0; s < 4; ++s) {
#pragma unroll
            for (int i = 0; i < 4; ++i) {
                int idx = i * 256 + tid;
                int row = idx >> 3, u = idx & 7;
                const void* src = srcs[s] + (size_t)row * D_MODEL + c * KC + u * 8;
                uint32_t dst = stage + s * 16384 + row * 128 + ((u ^ (row & 7)) << 4);
                CP_ASYNC16(dst, src);
            }
        }
        CP_COMMIT();
    };

    stage_load(0, 0);

#pragma unroll 1
    for (int c = 0; c < NCHUNK; ++c) {
        if (c + 1 < NCHUNK) { stage_load((c + 1) & 1, c + 1); CP_WAIT1(); }
        else                { CP_WAIT0(); }
        __syncthreads();

        const uint32_t stage = smem_base + (c & 1) * STAGE_BYTES;
        const uint32_t Ah = stage;
        const uint32_t Al = stage + 16384;
        const uint32_t Bh = stage + 32768;
        const uint32_t Bl = stage + 49152;

#pragma unroll
        for (int ks = 0; ks < 4; ++ks) {
            uint32_t ah[4][4], al[4][4], bh[2][4], bl[2][4];
#pragma unroll
            for (int mt = 0; mt < 4; ++mt) {
                int row  = wm * 64 + mt * 16 + a_row_off;
                int unit = ks * 2 + a_unit_off;
                uint32_t off = row * 128 + ((unit ^ (row & 7)) << 4);
                ldsm4(ah[mt], Ah + off);
                ldsm4(al[mt], Al + off);
            }
#pragma unroll
            for (int nh = 0; nh < 2; ++nh) {
                int row  = wn * 32 + nh * 16 + b_row_off;
                int unit = ks * 2 + b_unit_off;
                uint32_t off = row * 128 + ((unit ^ (row & 7)) << 4);
                ldsm4(bh[nh], Bh + off);
                ldsm4(bl[nh], Bl + off);
            }
#pragma unroll
            for (int mt = 0; mt < 4; ++mt) {
#pragma unroll
                for (int nt = 0; nt < 4; ++nt) {
                    const int nh = nt >> 1, p = (nt & 1) * 2;
                    mma_bf16(acc[mt][nt], ah[mt], bh[nh][p], bh[nh][p + 1]);
                    mma_bf16(acc[mt][nt], ah[mt], bl[nh][p], bl[nh][p + 1]);
                    mma_bf16(acc[mt][nt], al[mt], bh[nh][p], bh[nh][p + 1]);
                }
            }
        }
        __syncthreads();
    }

    const int grow = lane >> 2;
    const int gcol = (lane & 3) * 2;
#pragma unroll
    for (int mt = 0; mt < 4; ++mt) {
#pragma unroll
        for (int nt = 0; nt < 4; ++nt) {
            const int m0 = bm + wm * 64 + mt * 16 + grow;
            const int n0 = bn + wn * 32 + nt * 8 + gcol;
            const float b0 = bias[n0], b1 = bias[n0 + 1];
            float v00 = acc[mt][nt][0] + b0, v01 = acc[mt][nt][1] + b1;
            float v10 = acc[mt][nt][2] + b0, v11 = acc[mt][nt][3] + b1;
            if (outf) {
                *(float2*)&outf[(size_t)m0 * D_MODEL + n0]       = make_float2(v00, v01);
                *(float2*)&outf[(size_t)(m0 + 8) * D_MODEL + n0] = make_float2(v10, v11);
            } else {
                *(uint32_t*)&ohi[(size_t)m0 * D_MODEL + n0] = pack_hi(v00, v01);
                *(uint32_t*)&olo[(size_t)m0 * D_MODEL + n0] =
                    pack_rn(v00 - hi_part(v00), v01 - hi_part(v01));
                *(uint32_t*)&ohi[(size_t)(m0 + 8) * D_MODEL + n0] = pack_hi(v10, v11);
                *(uint32_t*)&olo[(size_t)(m0 + 8) * D_MODEL + n0] =
                    pack_rn(v10 - hi_part(v10), v11 - hi_part(v11));
            }
        }
    }
}

// ---------------------------------------------------------------------------
// Causal flash attention on mma.sync, bf16 hi/lo split for QK^T and PV.
// Block: 128 queries, 8 warps (16 q each). Key tiles of 64, double-buffered.
// Output written as bf16 hi/lo directly into the O-projection input buffers.
// ---------------------------------------------------------------------------
#define AQ 128                       // queries per block
#define AKT 64                       // keys per tile
// smem: Qhi 16K | Qlo 16K | stage0 {Khi,Klo,Vhi,Vlo}x8K | stage1
#define A_SQ_LO   16384
#define A_STAGES  32768
#define A_STAGE_SZ 32768
#define A_SM_TOTAL (A_STAGES + 2 * A_STAGE_SZ)   // 98304

__global__ __launch_bounds__(256, 1) void attn_mma(
    const __nv_bfloat16* __restrict__ qhi, const __nv_bfloat16* __restrict__ qlo,
    const __nv_bfloat16* __restrict__ khi, const __nv_bfloat16* __restrict__ klo,
    const __nv_bfloat16* __restrict__ vhi, const __nv_bfloat16* __restrict__ vlo,
    __nv_bfloat16* __restrict__ ohi, __nv_bfloat16* __restrict__ olo)
{
    extern __shared__ __align__(1024) char smem[];
    const uint32_t smem_base = smem_u32(smem);
    const int tid  = threadIdx.x;
    const int w    = tid >> 5;
    const int lane = tid & 31;
    const int qb = blockIdx.x;     // 0..15
    const int h  = blockIdx.y;
    const int b  = blockIdx.z;

    const int a_row_off  = ((lane >> 3) & 1) * 8 + (lane & 7);
    const int a_unit_off = lane >> 4;
    const int b_row_off  = ((lane >> 4) & 1) * 8 + (lane & 7);
    const int b_unit_off = (lane >> 3) & 1;
    const int grow = lane >> 2;
    const int gcol = (lane & 3) * 2;

    const int KT = 2 * qb + 2;     // number of 64-key tiles

    auto q_load = [&]() {
#pragma unroll
        for (int i = 0; i < 8; ++i) {
            int idx = i * 256 + tid;
            int t = idx >> 10, row = (idx >> 3) & 127, u = idx & 7;
            const __nv_bfloat16* src =
                (t ? qlo : qhi) + (size_t)(b * SEQ + qb * AQ + row) * D_MODEL + h * DK + u * 8;
            uint32_t dst = smem_base + t * 16384 + row * 128 + ((u ^ (row & 7)) << 4);
            CP_ASYNC16(dst, src);
        }
        CP_COMMIT();
    };
    auto stage_load = [&](int s, int kt) {
        const uint32_t base = smem_base + A_STAGES + s * A_STAGE_SZ;
#pragma unroll
        for (int i = 0; i < 8; ++i) {
            int idx = i * 256 + tid;
            int t = idx >> 9, row = (idx >> 3) & 63, u = idx & 7;
            const __nv_bfloat16* arr = (t == 0) ? khi : (t == 1) ? klo : (t == 2) ? vhi : vlo;
            const __nv_bfloat16* src =
                arr + (size_t)(b * SEQ + kt * AKT + row) * D_MODEL + h * DK + u * 8;
            uint32_t dst = base + t * 8192 + row * 128 + ((u ^ (row & 7)) << 4);
            CP_ASYNC16(dst, src);
        }
        CP_COMMIT();
    };

    q_load();
    stage_load(0, 0);

    uint32_t qh[4][4], ql[4][4];
    float of[8][4];
#pragma unroll
    for (int nt = 0; nt < 8; ++nt)
#pragma unroll
        for (int j = 0; j < 4; ++j) of[nt][j] = 0.f;
    float m0 = -1e30f, m1 = -1e30f, l0 = 0.f, l1 = 0.f;

    const int q0g = qb * AQ + w * 16 + grow;   // this thread's row 0 (in seq)
    const int q1g = q0g + 8;
    const int qmax_warp = qb * AQ + w * 16 + 15;
    const float NEG_INF = __int_as_float(0xff800000);

#pragma unroll 1
    for (int kt = 0; kt < KT; ++kt) {
        if (kt + 1 < KT) { stage_load((kt + 1) & 1, kt + 1); CP_WAIT1(); }
        else             { CP_WAIT0(); }
        __syncthreads();

        if (kt == 0) {
#pragma unroll
            for (int ks = 0; ks < 4; ++ks) {
                int row  = w * 16 + a_row_off;
                int unit = ks * 2 + a_unit_off;
                uint32_t off = row * 128 + ((unit ^ (row & 7)) << 4);
                ldsm4(qh[ks], smem_base + off);
                ldsm4(ql[ks], smem_base + A_SQ_LO + off);
            }
        }

        if (kt * AKT <= qmax_warp) {
            const uint32_t Kh = smem_base + A_STAGES + (kt & 1) * A_STAGE_SZ;
            const uint32_t Kl = Kh + 8192;
            const uint32_t Vh = Kh + 16384;
            const uint32_t Vl = Kh + 24576;

            // ---- S = Q K^T (3-term split) ----
            float sf[8][4];
#pragma unroll
            for (int nt = 0; nt < 8; ++nt)
#pragma unroll
                for (int j = 0; j < 4; ++j) sf[nt][j] = 0.f;

#pragma unroll
            for (int ks = 0; ks < 4; ++ks) {
#pragma unroll
                for (int nh = 0; nh < 4; ++nh) {
                    int row  = nh * 16 + b_row_off;
                    int unit = ks * 2 + b_unit_off;
                    uint32_t off = row * 128 + ((unit ^ (row & 7)) << 4);
                    uint32_t kh[4], kl[4];
                    ldsm4(kh, Kh + off);
                    ldsm4(kl, Kl + off);
                    mma_bf16(sf[2 * nh],     qh[ks], kh[0], kh[1]);
                    mma_bf16(sf[2 * nh],     qh[ks], kl[0], kl[1]);
                    mma_bf16(sf[2 * nh],     ql[ks], kh[0], kh[1]);
                    mma_bf16(sf[2 * nh + 1], qh[ks], kh[2], kh[3]);
                    mma_bf16(sf[2 * nh + 1], qh[ks], kl[2], kl[3]);
                    mma_bf16(sf[2 * nh + 1], ql[ks], kh[2], kh[3]);
                }
            }

            // ---- scale + causal mask ----
            const bool needmask = (kt >= 2 * qb);
#pragma unroll
            for (int nt = 0; nt < 8; ++nt) {
#pragma unroll
                for (int j = 0; j < 4; ++j) sf[nt][j] *= 0.125f;
                if (needmask) {
                    int c0 = kt * AKT + nt * 8 + gcol;
                    if (c0     > q0g) sf[nt][0] = NEG_INF;
                    if (c0 + 1 > q0g) sf[nt][1] = NEG_INF;
                    if (c0     > q1g) sf[nt][2] = NEG_INF;
                    if (c0 + 1 > q1g) sf[nt][3] = NEG_INF;
                }
            }

            // ---- online softmax ----
            float tm0 = sf[0][0], tm1 = sf[0][2];
#pragma unroll
            for (int nt = 0; nt < 8; ++nt) {
                tm0 = fmaxf(tm0, fmaxf(sf[nt][0], sf[nt][1]));
                tm1 = fmaxf(tm1, fmaxf(sf[nt][2], sf[nt][3]));
            }
            tm0 = fmaxf(tm0, __shfl_xor_sync(0xffffffffu, tm0, 1));
            tm0 = fmaxf(tm0, __shfl_xor_sync(0xffffffffu, tm0, 2));
            tm1 = fmaxf(tm1, __shfl_xor_sync(0xffffffffu, tm1, 1));
            tm1 = fmaxf(tm1, __shfl_xor_sync(0xffffffffu, tm1, 2));

            const float m0n = fmaxf(m0, tm0);
            const float m1n = fmaxf(m1, tm1);
            const float sc0 = __expf(m0 - m0n);
            const float sc1 = __expf(m1 - m1n);
            l0 *= sc0; l1 *= sc1;
#pragma unroll
            for (int nt = 0; nt < 8; ++nt) {
                of[nt][0] *= sc0; of[nt][1] *= sc0;
                of[nt][2] *= sc1; of[nt][3] *= sc1;
            }
            m0 = m0n; m1 = m1n;

            float p[8][4];
#pragma unroll
            for (int nt = 0; nt < 8; ++nt) {
                p[nt][0] = __expf(sf[nt][0] - m0n);
                p[nt][1] = __expf(sf[nt][1] - m0n);
                p[nt][2] = __expf(sf[nt][2] - m1n);
                p[nt][3] = __expf(sf[nt][3] - m1n);
                l0 += p[nt][0] + p[nt][1];
                l1 += p[nt][2] + p[nt][3];
            }

            // ---- pack P into A-frags (C m16n16 == A m16k16 correspondence) ----
            uint32_t pah[4][4], pal[4][4];
#pragma unroll
            for (int j = 0; j < 4; ++j) {
                pah[j][0] = pack_hi(p[2 * j][0],     p[2 * j][1]);
                pah[j][1] = pack_hi(p[2 * j][2],     p[2 * j][3]);
                pah[j][2] = pack_hi(p[2 * j + 1][0], p[2 * j + 1][1]);
                pah[j][3] = pack_hi(p[2 * j + 1][2], p[2 * j + 1][3]);
                pal[j][0] = pack_rn(p[2 * j][0] - hi_part(p[2 * j][0]),
                                    p[2 * j][1] - hi_part(p[2 * j][1]));
                pal[j][1] = pack_rn(p[2 * j][2] - hi_part(p[2 * j][2]),
                                    p[2 * j][3] - hi_part(p[2 * j][3]));
                pal[j][2] = pack_rn(p[2 * j + 1][0] - hi_part(p[2 * j + 1][0]),
                                    p[2 * j + 1][1] - hi_part(p[2 * j + 1][1]));
                pal[j][3] = pack_rn(p[2 * j + 1][2] - hi_part(p[2 * j + 1][2]),
                                    p[2 * j + 1][3] - hi_part(p[2 * j + 1][3]));
            }

            // ---- O += P V (3-term split), V via ldmatrix.trans ----
            const int vrow_off = ((lane >> 3) & 1) * 8 + (lane & 7);
            const int vunit_off = (lane >> 4) & 1;
#pragma unroll
            for (int ks = 0; ks < 4; ++ks) {
#pragma unroll
                for (int nh = 0; nh < 4; ++nh) {
                    int row  = ks * 16 + vrow_off;
                    int unit = nh * 2 + vunit_off;
                    uint32_t off = row * 128 + ((unit ^ (row & 7)) << 4);
                    uint32_t vh[4], vl[4];
                    ldsm4t(vh, Vh + off);
                    ldsm4t(vl, Vl + off);
                    mma_bf16(of[2 * nh],     pah[ks], vh[0], vh[1]);
                    mma_bf16(of[2 * nh],     pah[ks], vl[0], vl[1]);
                    mma_bf16(of[2 * nh],     pal[ks], vh[0], vh[1]);
                    mma_bf16(of[2 * nh + 1], pah[ks], vh[2], vh[3]);
                    mma_bf16(of[2 * nh + 1], pah[ks], vl[2], vl[3]);
                    mma_bf16(of[2 * nh + 1], pal[ks], vh[2], vh[3]);
                }
            }
        }
        __syncthreads();
    }

    // ---- epilogue: normalize, split to bf16 hi/lo, store ----
    l0 += __shfl_xor_sync(0xffffffffu, l0, 1);
    l0 += __shfl_xor_sync(0xffffffffu, l0, 2);
    l1 += __shfl_xor_sync(0xffffffffu, l1, 1);
    l1 += __shfl_xor_sync(0xffffffffu, l1, 2);
    const float inv0 = 1.f / l0;
    const float inv1 = 1.f / l1;

    const size_t r0 = (size_t)(b * SEQ + q0g);
    const size_t r1 = (size_t)(b * SEQ + q1g);
#pragma unroll
    for (int nt = 0; nt < 8; ++nt) {
        const int col = h * DK + nt * 8 + gcol;
        float v00 = of[nt][0] * inv0, v01 = of[nt][1] * inv0;
        float v10 = of[nt][2] * inv1, v11 = of[nt][3] * inv1;
        *(uint32_t*)&ohi[r0 * D_MODEL + col] = pack_hi(v00, v01);
        *(uint32_t*)&olo[r0 * D_MODEL + col] =
            pack_rn(v00 - hi_part(v00), v01 - hi_part(v01));
        *(uint32_t*)&ohi[r1 * D_MODEL + col] = pack_hi(v10, v11);
        *(uint32_t*)&olo[r1 * D_MODEL + col] =
            pack_rn(v10 - hi_part(v10), v11 - hi_part(v11));
    }
}

// ---------------------------------------------------------------------------
// Launch
// Inputs (metadata order): Q, K, V, mask, W_q, b_q, W_k, b_k, W_v, b_v, W_o, b_o
// ---------------------------------------------------------------------------
extern "C" void kernel_launch(void* const* d_in, const int* in_sizes, int n_in,
                              void* d_out, int out_size)
{
    const float* Q   = (const float*)d_in[0];
    const float* K   = (const float*)d_in[1];
    const float* V   = (const float*)d_in[2];
    const float* W_q = (const float*)d_in[4];
    const float* b_q = (const float*)d_in[5];
    const float* W_k = (const float*)d_in[6];
    const float* b_k = (const float*)d_in[7];
    const float* W_v = (const float*)d_in[8];
    const float* b_v = (const float*)d_in[9];
    const float* W_o = (const float*)d_in[10];
    const float* b_o = (const float*)d_in[11];
    float* out = (float*)d_out;

    __nv_bfloat16 *qhi, *qlo, *khi, *klo, *vhi, *vlo, *xhi, *xlo, *whi, *wlo;
    cudaGetSymbolAddress((void**)&qhi, g_qhi);
    cudaGetSymbolAddress((void**)&qlo, g_qlo);
    cudaGetSymbolAddress((void**)&khi, g_khi);
    cudaGetSymbolAddress((void**)&klo, g_klo);
    cudaGetSymbolAddress((void**)&vhi, g_vhi);
    cudaGetSymbolAddress((void**)&vlo, g_vlo);
    cudaGetSymbolAddress((void**)&xhi, g_xhi);
    cudaGetSymbolAddress((void**)&xlo, g_xlo);
    cudaGetSymbolAddress((void**)&whi, g_whi);
    cudaGetSymbolAddress((void**)&wlo, g_wlo);

    cudaFuncSetAttribute(gemm_mma, cudaFuncAttributeMaxDynamicSharedMemorySize, SM_TOTAL);
    cudaFuncSetAttribute(attn_mma, cudaFuncAttributeMaxDynamicSharedMemorySize, A_SM_TOTAL);

    const int nX4 = M_TOTAL * D_MODEL / 4;
    const int nW4 = D_MODEL * D_MODEL / 4;
    const int SPLIT_B = 256;
    dim3 gX((nX4 + SPLIT_B - 1) / SPLIT_B);
    dim3 gW((nW4 + SPLIT_B - 1) / SPLIT_B);
    dim3 gGemm(D_MODEL / TN, M_TOTAL / TM);   // (8, 64)

    // Q projection -> qhi/qlo
    split_kernel<<<gX, SPLIT_B>>>(Q, xhi, xlo, nX4);
    split_kernel<<<gW, SPLIT_B>>>(W_q, whi, wlo, nW4);
    gemm_mma<<<gGemm, 256, SM_TOTAL>>>(xhi, xlo, whi, wlo, b_q, nullptr, qhi, qlo);
    // K projection -> khi/klo
    split_kernel<<<gX, SPLIT_B>>>(K, xhi, xlo, nX4);
    split_kernel<<<gW, SPLIT_B>>>(W_k, whi, wlo, nW4);
    gemm_mma<<<gGemm, 256, SM_TOTAL>>>(xhi, xlo, whi, wlo, b_k, nullptr, khi, klo);
    // V projection -> vhi/vlo
    split_kernel<<<gX, SPLIT_B>>>(V, xhi, xlo, nX4);
    split_kernel<<<gW, SPLIT_B>>>(W_v, whi, wlo, nW4);
    gemm_mma<<<gGemm, 256, SM_TOTAL>>>(xhi, xlo, whi, wlo, b_v, nullptr, vhi, vlo);

    // attention -> writes xhi/xlo (input of O projection)
    dim3 gAttn(SEQ / AQ, N_HEADS, BATCH);     // (16, 16, 4)
    attn_mma<<<gAttn, 256, A_SM_TOTAL>>>(qhi, qlo, khi, klo, vhi, vlo, xhi, xlo);

    // O projection -> fp32 out
    split_kernel<<<gW, SPLIT_B>>>(W_o, whi, wlo, nW4);
    gemm_mma<<<gGemm, 256, SM_TOTAL>>>(xhi, xlo, whi, wlo, b_o, out, nullptr, nullptr);
}